// round 3
// baseline (speedup 1.0000x reference)
#include <cuda_runtime.h>

// Problem constants (fixed by reference: B=8, T=4096, C=32, D=64)
#define B_  8
#define T_  4096
#define C_  32
#define D_  64
#define NQT (T_ / 64)     // 64 query tiles per batch

#define KSTR 68           // padded stride for d-major Q/K tiles (float4-aligned, conflict-free reads)
#define PSTR 68           // padded stride for P tile

// Scratch for projected Q, K, V: 8 MB each (device globals — no allocation)
__device__ float g_q[B_ * T_ * D_];
__device__ float g_k[B_ * T_ * D_];
__device__ float g_v[B_ * T_ * D_];

// ---------------------------------------------------------------------------
// Kernel 1: Q/K/V projection.  One CTA = 64 rows of flattened (b,t).
// ---------------------------------------------------------------------------
__global__ __launch_bounds__(256) void proj_kernel(
    const float* __restrict__ x,  const float* __restrict__ Wk,
    const float* __restrict__ Wq, const float* __restrict__ Wv)
{
    __shared__ float xs[64][36];       // 64 rows x 32 cols (padded)
    __shared__ float Ws[3][32][64];    // Wk, Wq, Wv

    const int tid  = threadIdx.x;
    const int row0 = blockIdx.x * 64;

    // Load x tile (64x32 = 512 float4), coalesced
    {
        const float4* xg = (const float4*)(x + row0 * C_);
        #pragma unroll
        for (int it = 0; it < 2; it++) {
            int lin = tid + it * 256;            // 0..511
            int r = lin >> 3, c4 = lin & 7;      // 8 float4 per row
            *(float4*)&xs[r][c4 * 4] = xg[lin];
        }
    }
    // Load weights (each 32x64 = 512 float4)
    {
        const float4* srcs[3] = {(const float4*)Wk, (const float4*)Wq, (const float4*)Wv};
        #pragma unroll
        for (int m = 0; m < 3; m++) {
            float4* dst = (float4*)&Ws[m][0][0];
            #pragma unroll
            for (int it = 0; it < 2; it++)
                dst[tid + it * 256] = srcs[m][tid + it * 256];
        }
    }
    __syncthreads();

    const int tx = tid & 15, ty = tid >> 4;      // 16x16 thread grid, 4x4 tiles
    float* outs[3] = {g_k, g_q, g_v};            // matches Wk, Wq, Wv order

    #pragma unroll
    for (int m = 0; m < 3; m++) {
        float acc[4][4];
        #pragma unroll
        for (int i = 0; i < 4; i++)
            #pragma unroll
            for (int j = 0; j < 4; j++) acc[i][j] = 0.f;

        #pragma unroll
        for (int c = 0; c < 32; c++) {
            float4 w = *(const float4*)&Ws[m][c][tx * 4];
            #pragma unroll
            for (int i = 0; i < 4; i++) {
                float xv = xs[ty * 4 + i][c];
                acc[i][0] += xv * w.x; acc[i][1] += xv * w.y;
                acc[i][2] += xv * w.z; acc[i][3] += xv * w.w;
            }
        }
        float* o = outs[m] + row0 * D_;
        #pragma unroll
        for (int i = 0; i < 4; i++)
            *(float4*)&o[(ty * 4 + i) * D_ + tx * 4] =
                make_float4(acc[i][0], acc[i][1], acc[i][2], acc[i][3]);
    }
}

// ---------------------------------------------------------------------------
// Kernel 2: flash attention (causal, NO 1/sqrt(D) scaling).
// One CTA = (batch b, 64-query tile qt).  256 threads = 16x16 grid, 4x4 tiles.
// ---------------------------------------------------------------------------
__global__ __launch_bounds__(256, 2) void attn_kernel(float* __restrict__ out)
{
    extern __shared__ float sm[];
    float* Qs = sm;                                 // [d=64][KSTR]  (d-major / transposed)
    float* Ks = sm + 64 * KSTR;                     // [d=64][KSTR]
    float* Vs = sm + 2 * 64 * KSTR;                 // [k=64][64]    (natural)
    float* Ps = sm + 2 * 64 * KSTR + 64 * 64;       // [q=64][PSTR]

    const int b   = blockIdx.y;
    const int qt  = (NQT - 1) - blockIdx.x;         // heaviest tiles launch first
    const int tid = threadIdx.x;
    const int tx  = tid & 15, ty = tid >> 4;

    // Load + transpose Q tile -> Qs[d][q]
    {
        const float* Qg = g_q + (b * T_ + qt * 64) * D_;
        #pragma unroll
        for (int it = 0; it < 4; it++) {
            int lin = tid + it * 256;               // 0..1023
            int r = lin >> 4, d4 = lin & 15;
            float4 v = *(const float4*)&Qg[r * D_ + d4 * 4];
            Qs[(d4 * 4 + 0) * KSTR + r] = v.x;
            Qs[(d4 * 4 + 1) * KSTR + r] = v.y;
            Qs[(d4 * 4 + 2) * KSTR + r] = v.z;
            Qs[(d4 * 4 + 3) * KSTR + r] = v.w;
        }
    }

    float acc[4][4];
    float m_i[4], l_i[4];
    #pragma unroll
    for (int i = 0; i < 4; i++) {
        m_i[i] = -1e30f; l_i[i] = 0.f;
        #pragma unroll
        for (int j = 0; j < 4; j++) acc[i][j] = 0.f;
    }

    for (int kt = 0; kt <= qt; kt++) {
        __syncthreads();   // prev PV done (and Qs visible on first iter)

        // Load K tile (transposed -> Ks[d][k]) and V tile (natural)
        {
            const float* Kg = g_k + (b * T_ + kt * 64) * D_;
            const float* Vg = g_v + (b * T_ + kt * 64) * D_;
            #pragma unroll
            for (int it = 0; it < 4; it++) {
                int lin = tid + it * 256;
                int r = lin >> 4, d4 = lin & 15;
                float4 v = *(const float4*)&Kg[r * D_ + d4 * 4];
                Ks[(d4 * 4 + 0) * KSTR + r] = v.x;
                Ks[(d4 * 4 + 1) * KSTR + r] = v.y;
                Ks[(d4 * 4 + 2) * KSTR + r] = v.z;
                Ks[(d4 * 4 + 3) * KSTR + r] = v.w;
                ((float4*)Vs)[lin] = ((const float4*)Vg)[lin];
            }
        }
        __syncthreads();

        // ---- S = Q K^T for this tile (4q x 4k per thread) ----
        float s[4][4];
        #pragma unroll
        for (int i = 0; i < 4; i++)
            #pragma unroll
            for (int j = 0; j < 4; j++) s[i][j] = 0.f;

        #pragma unroll 4
        for (int d = 0; d < 64; d++) {
            float4 q4 = *(const float4*)&Qs[d * KSTR + ty * 4];
            float4 k4 = *(const float4*)&Ks[d * KSTR + tx * 4];
            float qa[4] = {q4.x, q4.y, q4.z, q4.w};
            float ka[4] = {k4.x, k4.y, k4.z, k4.w};
            #pragma unroll
            for (int i = 0; i < 4; i++)
                #pragma unroll
                for (int j = 0; j < 4; j++)
                    s[i][j] += qa[i] * ka[j];
        }

        // Causal mask (only the diagonal tile needs it; kt < qt is fully valid)
        if (kt == qt) {
            #pragma unroll
            for (int i = 0; i < 4; i++)
                #pragma unroll
                for (int j = 0; j < 4; j++)
                    if (tx * 4 + j > ty * 4 + i) s[i][j] = -1e30f;
        }

        // ---- online softmax update (rows distributed over 16 tx lanes) ----
        #pragma unroll
        for (int i = 0; i < 4; i++) {
            float mx = fmaxf(fmaxf(s[i][0], s[i][1]), fmaxf(s[i][2], s[i][3]));
            mx = fmaxf(mx, __shfl_xor_sync(0xffffffffu, mx, 8));
            mx = fmaxf(mx, __shfl_xor_sync(0xffffffffu, mx, 4));
            mx = fmaxf(mx, __shfl_xor_sync(0xffffffffu, mx, 2));
            mx = fmaxf(mx, __shfl_xor_sync(0xffffffffu, mx, 1));
            float mnew = fmaxf(m_i[i], mx);
            float corr = __expf(m_i[i] - mnew);     // 0 on first tile (m=-1e30)
            float rs = 0.f;
            #pragma unroll
            for (int j = 0; j < 4; j++) {
                float p = __expf(s[i][j] - mnew);
                s[i][j] = p;
                rs += p;
            }
            rs += __shfl_xor_sync(0xffffffffu, rs, 8);
            rs += __shfl_xor_sync(0xffffffffu, rs, 4);
            rs += __shfl_xor_sync(0xffffffffu, rs, 2);
            rs += __shfl_xor_sync(0xffffffffu, rs, 1);
            l_i[i] = l_i[i] * corr + rs;
            m_i[i] = mnew;
            #pragma unroll
            for (int j = 0; j < 4; j++) acc[i][j] *= corr;
            #pragma unroll
            for (int j = 0; j < 4; j++)
                Ps[(ty * 4 + i) * PSTR + tx * 4 + j] = s[i][j];
        }
        __syncthreads();   // Ps visible to all

        // ---- O += P V  (4q x 4d per thread; tx now indexes d) ----
        #pragma unroll 2
        for (int kk = 0; kk < 16; kk++) {
            float4 v0 = *(const float4*)&Vs[(kk * 4 + 0) * 64 + tx * 4];
            float4 v1 = *(const float4*)&Vs[(kk * 4 + 1) * 64 + tx * 4];
            float4 v2 = *(const float4*)&Vs[(kk * 4 + 2) * 64 + tx * 4];
            float4 v3 = *(const float4*)&Vs[(kk * 4 + 3) * 64 + tx * 4];
            #pragma unroll
            for (int i = 0; i < 4; i++) {
                float4 pi = *(const float4*)&Ps[(ty * 4 + i) * PSTR + kk * 4];
                acc[i][0] += pi.x * v0.x + pi.y * v1.x + pi.z * v2.x + pi.w * v3.x;
                acc[i][1] += pi.x * v0.y + pi.y * v1.y + pi.z * v2.y + pi.w * v3.y;
                acc[i][2] += pi.x * v0.z + pi.y * v1.z + pi.z * v2.z + pi.w * v3.z;
                acc[i][3] += pi.x * v0.w + pi.y * v1.w + pi.z * v2.w + pi.w * v3.w;
            }
        }
    }

    // Normalize and write output
    float* Og = out + (b * T_ + qt * 64) * D_;
    #pragma unroll
    for (int i = 0; i < 4; i++) {
        float inv = 1.f / l_i[i];
        *(float4*)&Og[(ty * 4 + i) * D_ + tx * 4] =
            make_float4(acc[i][0] * inv, acc[i][1] * inv,
                        acc[i][2] * inv, acc[i][3] * inv);
    }
}

// ---------------------------------------------------------------------------
extern "C" void kernel_launch(void* const* d_in, const int* in_sizes, int n_in,
                              void* d_out, int out_size)
{
    const float* x  = (const float*)d_in[0];
    const float* Wk = (const float*)d_in[1];
    const float* Wq = (const float*)d_in[2];
    const float* Wv = (const float*)d_in[3];
    float* out = (float*)d_out;

    proj_kernel<<<(B_ * T_) / 64, 256>>>(x, Wk, Wq, Wv);

    const int smem = (2 * 64 * KSTR + 64 * 64 + 64 * PSTR) * (int)sizeof(float); // 68608 B
    cudaFuncSetAttribute(attn_kernel, cudaFuncAttributeMaxDynamicSharedMemorySize, smem);
    attn_kernel<<<dim3(NQT, B_), 256, smem>>>(out);
}

// round 4
// speedup vs baseline: 1.9298x; 1.9298x over previous
#include <cuda_runtime.h>

// Problem constants: B=8, T=4096, C=32 (embedding), D=64 (head)
#define B_  8
#define T_  4096
#define C_  32
#define D_  64
#define NQT (T_ / 64)

#define QP  68    // stride for transposed y / x tiles ([c][pos])
#define PP  68    // stride for P tile
#define XNP 36    // stride for natural x tile rows

// M = Wq * Wk^T  (32x32), computed once per launch by a tiny kernel.
__device__ float g_M[C_ * C_];

// ---------------------------------------------------------------------------
// Kernel 0: M[i][j] = sum_d Wq[i][d] * Wk[j][d]
// ---------------------------------------------------------------------------
__global__ void m_kernel(const float* __restrict__ Wk, const float* __restrict__ Wq)
{
    const int i = threadIdx.x >> 5;   // 0..31
    const int j = threadIdx.x & 31;   // 0..31
    float s = 0.f;
    #pragma unroll
    for (int d = 0; d < D_; d++)
        s += Wq[i * D_ + d] * Wk[j * D_ + d];
    g_M[i * C_ + j] = s;
}

// ---------------------------------------------------------------------------
// Kernel 1: fused causal attention via the M-trick.
//   y = x_q * M                       (per CTA, once)
//   S_t = y * x_k^T                   (inner dim 32)
//   online softmax -> P_t
//   Z += P_t * x_k                    (Z is 64x32)
//   out = (Z / l) * Wv                (per CTA, once)
// One CTA = (batch, 64-query tile). 256 threads.
// ---------------------------------------------------------------------------
__global__ __launch_bounds__(256, 3) void attn_kernel(
    const float* __restrict__ x, const float* __restrict__ Wv,
    float* __restrict__ out)
{
    __shared__ float ys[C_][QP];      // y transposed: ys[c'][q]
    __shared__ float xT[C_][QP];      // x_k transposed: xT[c][k]   (reused for Wv in epilogue)
    __shared__ float xN[64][XNP];     // x_k natural:    xN[k][c]
    __shared__ float Ps[64][PP];      // P tile          (reused for Z in epilogue)
    __shared__ float corr_s[64];
    __shared__ float linv_s[64];

    const int b   = blockIdx.y;
    const int qt  = (NQT - 1) - blockIdx.x;   // heaviest query tiles first
    const int tid = threadIdx.x;
    const int tx  = tid & 15, ty = tid >> 4;  // 16x16 grid (S-pass mapping)
    const int zr  = (tid >> 3) * 2;           // Z-pass mapping: rows zr, zr+1
    const int zc  = (tid & 7) * 4;            //                 cols zc..zc+3

    const float* xb = x + b * T_ * C_;

    // ---- load x_q (natural) and compute y = x_q * M, stored transposed ----
    {
        const float4* xg = (const float4*)(xb + qt * 64 * C_);
        #pragma unroll
        for (int it = 0; it < 2; it++) {
            int lin = tid + it * 256;           // 0..511 (64 rows x 8 float4)
            int r = lin >> 3, c4 = lin & 7;
            *(float4*)&xN[r][c4 * 4] = xg[lin];
        }
    }
    __syncthreads();
    {
        const int c0 = tx * 2;                  // this thread's 2 output cols
        float a0[4], a1[4];
        #pragma unroll
        for (int i = 0; i < 4; i++) { a0[i] = 0.f; a1[i] = 0.f; }
        #pragma unroll
        for (int c = 0; c < C_; c++) {
            float2 m2 = *(const float2*)&g_M[c * C_ + c0];
            #pragma unroll
            for (int i = 0; i < 4; i++) {
                float xv = xN[ty * 4 + i][c];
                a0[i] += xv * m2.x;
                a1[i] += xv * m2.y;
            }
        }
        #pragma unroll
        for (int i = 0; i < 4; i++) {
            ys[c0 + 0][ty * 4 + i] = a0[i];
            ys[c0 + 1][ty * 4 + i] = a1[i];
        }
    }

    float m_i[4], l_i[4];
    #pragma unroll
    for (int i = 0; i < 4; i++) { m_i[i] = -1e30f; l_i[i] = 0.f; }
    float z0[4], z1[4];
    #pragma unroll
    for (int j = 0; j < 4; j++) { z0[j] = 0.f; z1[j] = 0.f; }

    for (int kt = 0; kt <= qt; kt++) {
        __syncthreads();   // prev Z-pass done with xN/Ps/corr; ys ready on iter 0

        // ---- load x_k: natural + transposed copies ----
        {
            const float4* xg = (const float4*)(xb + kt * 64 * C_);
            #pragma unroll
            for (int it = 0; it < 2; it++) {
                int lin = tid + it * 256;
                int r = lin >> 3, c4 = lin & 7;
                float4 v = xg[lin];
                *(float4*)&xN[r][c4 * 4] = v;
                xT[c4 * 4 + 0][r] = v.x;
                xT[c4 * 4 + 1][r] = v.y;
                xT[c4 * 4 + 2][r] = v.z;
                xT[c4 * 4 + 3][r] = v.w;
            }
        }
        __syncthreads();

        // ---- S = y * x_k^T  (inner dim 32), 4q x 4k per thread ----
        float s[4][4];
        #pragma unroll
        for (int i = 0; i < 4; i++)
            #pragma unroll
            for (int j = 0; j < 4; j++) s[i][j] = 0.f;

        #pragma unroll
        for (int c = 0; c < C_; c++) {
            float4 q4 = *(const float4*)&ys[c][ty * 4];
            float4 k4 = *(const float4*)&xT[c][tx * 4];
            float qa[4] = {q4.x, q4.y, q4.z, q4.w};
            float ka[4] = {k4.x, k4.y, k4.z, k4.w};
            #pragma unroll
            for (int i = 0; i < 4; i++)
                #pragma unroll
                for (int j = 0; j < 4; j++)
                    s[i][j] += qa[i] * ka[j];
        }

        if (kt == qt) {   // diagonal tile: causal mask
            #pragma unroll
            for (int i = 0; i < 4; i++)
                #pragma unroll
                for (int j = 0; j < 4; j++)
                    if (tx * 4 + j > ty * 4 + i) s[i][j] = -1e30f;
        }

        // ---- online softmax (rows spread over the 16 tx lanes) ----
        #pragma unroll
        for (int i = 0; i < 4; i++) {
            float mx = fmaxf(fmaxf(s[i][0], s[i][1]), fmaxf(s[i][2], s[i][3]));
            mx = fmaxf(mx, __shfl_xor_sync(0xffffffffu, mx, 8));
            mx = fmaxf(mx, __shfl_xor_sync(0xffffffffu, mx, 4));
            mx = fmaxf(mx, __shfl_xor_sync(0xffffffffu, mx, 2));
            mx = fmaxf(mx, __shfl_xor_sync(0xffffffffu, mx, 1));
            float mnew = fmaxf(m_i[i], mx);
            float corr = __expf(m_i[i] - mnew);   // 0 on first tile
            float rs = 0.f;
            #pragma unroll
            for (int j = 0; j < 4; j++) {
                float p = __expf(s[i][j] - mnew);
                s[i][j] = p;
                rs += p;
            }
            rs += __shfl_xor_sync(0xffffffffu, rs, 8);
            rs += __shfl_xor_sync(0xffffffffu, rs, 4);
            rs += __shfl_xor_sync(0xffffffffu, rs, 2);
            rs += __shfl_xor_sync(0xffffffffu, rs, 1);
            l_i[i] = l_i[i] * corr + rs;
            m_i[i] = mnew;
            if (tx == 0) corr_s[ty * 4 + i] = corr;
            *(float4*)&Ps[ty * 4 + i][tx * 4] =
                make_float4(s[i][0], s[i][1], s[i][2], s[i][3]);
        }
        __syncthreads();

        // ---- Z += P * x_k  (2q x 4c per thread) ----
        float cr0 = corr_s[zr], cr1 = corr_s[zr + 1];
        #pragma unroll
        for (int j = 0; j < 4; j++) { z0[j] *= cr0; z1[j] *= cr1; }

        #pragma unroll 4
        for (int k4 = 0; k4 < 16; k4++) {
            float4 xv0 = *(const float4*)&xN[k4 * 4 + 0][zc];
            float4 xv1 = *(const float4*)&xN[k4 * 4 + 1][zc];
            float4 xv2 = *(const float4*)&xN[k4 * 4 + 2][zc];
            float4 xv3 = *(const float4*)&xN[k4 * 4 + 3][zc];
            float4 p0  = *(const float4*)&Ps[zr + 0][k4 * 4];
            float4 p1  = *(const float4*)&Ps[zr + 1][k4 * 4];
            z0[0] += p0.x * xv0.x + p0.y * xv1.x + p0.z * xv2.x + p0.w * xv3.x;
            z0[1] += p0.x * xv0.y + p0.y * xv1.y + p0.z * xv2.y + p0.w * xv3.y;
            z0[2] += p0.x * xv0.z + p0.y * xv1.z + p0.z * xv2.z + p0.w * xv3.z;
            z0[3] += p0.x * xv0.w + p0.y * xv1.w + p0.z * xv2.w + p0.w * xv3.w;
            z1[0] += p1.x * xv0.x + p1.y * xv1.x + p1.z * xv2.x + p1.w * xv3.x;
            z1[1] += p1.x * xv0.y + p1.y * xv1.y + p1.z * xv2.y + p1.w * xv3.y;
            z1[2] += p1.x * xv0.z + p1.y * xv1.z + p1.z * xv2.z + p1.w * xv3.z;
            z1[3] += p1.x * xv0.w + p1.y * xv1.w + p1.z * xv2.w + p1.w * xv3.w;
        }
    }

    // ---- epilogue: out = (Z / l) * Wv ----
    if (tx == 0) {
        #pragma unroll
        for (int i = 0; i < 4; i++) linv_s[ty * 4 + i] = 1.f / l_i[i];
    }
    __syncthreads();   // all Z-pass reads of Ps done; linv visible

    {
        float i0 = linv_s[zr], i1 = linv_s[zr + 1];
        *(float4*)&Ps[zr + 0][zc] = make_float4(z0[0]*i0, z0[1]*i0, z0[2]*i0, z0[3]*i0);
        *(float4*)&Ps[zr + 1][zc] = make_float4(z1[0]*i1, z1[1]*i1, z1[2]*i1, z1[3]*i1);
    }
    {   // load Wv [32][64] into xT (row-major, padded stride QP)
        const float4* wg = (const float4*)Wv;
        #pragma unroll
        for (int it = 0; it < 2; it++) {
            int lin = tid + it * 256;           // 0..511 (32 rows x 16 float4)
            int r = lin >> 4, c4 = lin & 15;
            *(float4*)&xT[r][c4 * 4] = wg[lin];
        }
    }
    __syncthreads();

    float o[4][4];
    #pragma unroll
    for (int i = 0; i < 4; i++)
        #pragma unroll
        for (int j = 0; j < 4; j++) o[i][j] = 0.f;

    #pragma unroll
    for (int c = 0; c < C_; c++) {
        float4 w4 = *(const float4*)&xT[c][tx * 4];
        #pragma unroll
        for (int i = 0; i < 4; i++) {
            float zv = Ps[ty * 4 + i][c];
            o[i][0] += zv * w4.x; o[i][1] += zv * w4.y;
            o[i][2] += zv * w4.z; o[i][3] += zv * w4.w;
        }
    }

    float* Og = out + (b * T_ + qt * 64) * D_;
    #pragma unroll
    for (int i = 0; i < 4; i++)
        *(float4*)&Og[(ty * 4 + i) * D_ + tx * 4] =
            make_float4(o[i][0], o[i][1], o[i][2], o[i][3]);
}

// ---------------------------------------------------------------------------
extern "C" void kernel_launch(void* const* d_in, const int* in_sizes, int n_in,
                              void* d_out, int out_size)
{
    const float* x  = (const float*)d_in[0];
    const float* Wk = (const float*)d_in[1];
    const float* Wq = (const float*)d_in[2];
    const float* Wv = (const float*)d_in[3];
    float* out = (float*)d_out;

    m_kernel<<<1, 1024>>>(Wk, Wq);
    attn_kernel<<<dim3(NQT, B_), 256>>>(x, Wv, out);
}

// round 5
// speedup vs baseline: 2.0404x; 1.0573x over previous
#include <cuda_runtime.h>

// Problem constants: B=8, T=4096, C=32 (embedding), D=64 (head)
#define B_  8
#define T_  4096
#define C_  32
#define D_  64
#define NQT (T_ / 64)

#define QP  68    // stride for transposed y / x tiles ([c][pos])
#define PP  68    // stride for P tile
#define XNP 36    // stride for natural x tile rows

typedef unsigned long long ull;

// M = Wq * Wk^T  (32x32)
__device__ float g_M[C_ * C_];

// ---------------------------------------------------------------------------
// packed f32x2 helpers (sm_103a FFMA2 path)
// ---------------------------------------------------------------------------
__device__ __forceinline__ ull pack2(float a, float b) {
    ull r; asm("mov.b64 %0, {%1, %2};" : "=l"(r) : "f"(a), "f"(b)); return r;
}
__device__ __forceinline__ float2 unpack2(ull v) {
    float2 r; asm("mov.b64 {%0, %1}, %2;" : "=f"(r.x), "=f"(r.y) : "l"(v)); return r;
}
__device__ __forceinline__ void fma2(ull& d, ull a, ull b) {
    asm("fma.rn.f32x2 %0, %1, %2, %0;" : "+l"(d) : "l"(a), "l"(b));
}
__device__ __forceinline__ void mul2(ull& d, ull a) {
    asm("mul.rn.f32x2 %0, %0, %1;" : "+l"(d) : "l"(a));
}

// ---------------------------------------------------------------------------
// Kernel 0: M[i][j] = sum_d Wq[i][d] * Wk[j][d]
// ---------------------------------------------------------------------------
__global__ void m_kernel(const float* __restrict__ Wk, const float* __restrict__ Wq)
{
    const int i = threadIdx.x >> 5;
    const int j = threadIdx.x & 31;
    float s = 0.f;
    #pragma unroll
    for (int d = 0; d < D_; d++)
        s += Wq[i * D_ + d] * Wk[j * D_ + d];
    g_M[i * C_ + j] = s;
}

// ---------------------------------------------------------------------------
// Kernel 1: fused causal attention (M-trick), 128 threads/CTA.
//   y = x_q * M;  S = y x_k^T (inner 32);  online softmax;  Z += P x_k;
//   out = (Z/l) * Wv.
// S-pass: 16(tx) x 8(ty) grid, 8q x 4k per thread, FFMA2 paired along q.
// Z-pass: 4q x 4c per thread, FFMA2 paired along c.
// ---------------------------------------------------------------------------
__global__ __launch_bounds__(128, 4) void attn_kernel(
    const float* __restrict__ x, const float* __restrict__ Wv,
    float* __restrict__ out)
{
    __shared__ __align__(16) float ys[C_][QP];   // y transposed: ys[c'][q]
    __shared__ __align__(16) float xT[C_][QP];   // x_k transposed (reused for Wv)
    __shared__ __align__(16) float xN[64][XNP];  // x_k natural
    __shared__ __align__(16) float Ps[64][PP];   // P tile (reused for Z/l)
    __shared__ float corr_s[64];
    __shared__ float linv_s[64];

    const int b   = blockIdx.y;
    const int qt  = (NQT - 1) - blockIdx.x;      // heaviest tiles first
    const int tid = threadIdx.x;
    const int tx  = tid & 15, ty = tid >> 4;     // S-pass: 16x8 grid
    const int zr  = (tid >> 3) * 4;              // Z-pass rows zr..zr+3
    const int zc  = (tid & 7) * 4;               // Z-pass cols zc..zc+3

    const float* xb = x + b * T_ * C_;

    // ---- load x_q (natural) ----
    {
        const float4* xg = (const float4*)(xb + qt * 64 * C_);
        #pragma unroll
        for (int it = 0; it < 4; it++) {
            int lin = tid + it * 128;            // 0..511
            int r = lin >> 3, c4 = lin & 7;
            *(float4*)&xN[r][c4 * 4] = xg[lin];
        }
    }
    __syncthreads();

    // ---- y = x_q * M, stored transposed: rows ty*8..+7, cols tx*2..+1 ----
    {
        const int c0 = tx * 2;
        float a0[8], a1[8];
        #pragma unroll
        for (int i = 0; i < 8; i++) { a0[i] = 0.f; a1[i] = 0.f; }
        #pragma unroll 8
        for (int c = 0; c < C_; c++) {
            float2 m2 = *(const float2*)&g_M[c * C_ + c0];
            #pragma unroll
            for (int i = 0; i < 8; i++) {
                float xv = xN[ty * 8 + i][c];
                a0[i] += xv * m2.x;
                a1[i] += xv * m2.y;
            }
        }
        #pragma unroll
        for (int i = 0; i < 8; i++) {
            ys[c0 + 0][ty * 8 + i] = a0[i];
            ys[c0 + 1][ty * 8 + i] = a1[i];
        }
    }

    float m_i[8], l_i[8];
    #pragma unroll
    for (int i = 0; i < 8; i++) { m_i[i] = -1e30f; l_i[i] = 0.f; }
    ull z2[4][2];                                 // rows zr+i, col pairs (zc,zc+1),(zc+2,zc+3)
    #pragma unroll
    for (int i = 0; i < 4; i++) { z2[i][0] = 0ull; z2[i][1] = 0ull; }

    for (int kt = 0; kt <= qt; kt++) {
        __syncthreads();   // prev Z-pass done with xN/Ps; ys ready on iter 0

        // ---- load x_k: natural + transposed ----
        {
            const float4* xg = (const float4*)(xb + kt * 64 * C_);
            #pragma unroll
            for (int it = 0; it < 4; it++) {
                int lin = tid + it * 128;
                int r = lin >> 3, c4 = lin & 7;
                float4 v = xg[lin];
                *(float4*)&xN[r][c4 * 4] = v;
                xT[c4 * 4 + 0][r] = v.x;
                xT[c4 * 4 + 1][r] = v.y;
                xT[c4 * 4 + 2][r] = v.z;
                xT[c4 * 4 + 3][r] = v.w;
            }
        }
        __syncthreads();

        // ---- S = y * x_k^T : 8q x 4k per thread, q-paired FFMA2 ----
        ull s2[4][4];   // [j][i2]: (s[2*i2][j], s[2*i2+1][j])
        #pragma unroll
        for (int j = 0; j < 4; j++)
            #pragma unroll
            for (int i2 = 0; i2 < 4; i2++) s2[j][i2] = 0ull;

        #pragma unroll 8
        for (int c = 0; c < C_; c++) {
            float4 qa = *(const float4*)&ys[c][ty * 8];
            float4 qb = *(const float4*)&ys[c][ty * 8 + 4];
            float4 kv = *(const float4*)&xT[c][tx * 4];
            ull qp[4] = { pack2(qa.x, qa.y), pack2(qa.z, qa.w),
                          pack2(qb.x, qb.y), pack2(qb.z, qb.w) };
            ull kd[4] = { pack2(kv.x, kv.x), pack2(kv.y, kv.y),
                          pack2(kv.z, kv.z), pack2(kv.w, kv.w) };
            #pragma unroll
            for (int j = 0; j < 4; j++)
                #pragma unroll
                for (int i2 = 0; i2 < 4; i2++)
                    fma2(s2[j][i2], qp[i2], kd[j]);
        }

        float s[8][4];
        #pragma unroll
        for (int j = 0; j < 4; j++)
            #pragma unroll
            for (int i2 = 0; i2 < 4; i2++) {
                float2 u = unpack2(s2[j][i2]);
                s[2 * i2 + 0][j] = u.x;
                s[2 * i2 + 1][j] = u.y;
            }

        if (kt == qt) {   // causal mask on diagonal tile
            #pragma unroll
            for (int i = 0; i < 8; i++)
                #pragma unroll
                for (int j = 0; j < 4; j++)
                    if (tx * 4 + j > ty * 8 + i) s[i][j] = -1e30f;
        }

        // ---- online softmax (rows over 16 tx lanes) ----
        #pragma unroll
        for (int i = 0; i < 8; i++) {
            float mx = fmaxf(fmaxf(s[i][0], s[i][1]), fmaxf(s[i][2], s[i][3]));
            mx = fmaxf(mx, __shfl_xor_sync(0xffffffffu, mx, 8));
            mx = fmaxf(mx, __shfl_xor_sync(0xffffffffu, mx, 4));
            mx = fmaxf(mx, __shfl_xor_sync(0xffffffffu, mx, 2));
            mx = fmaxf(mx, __shfl_xor_sync(0xffffffffu, mx, 1));
            float mnew = fmaxf(m_i[i], mx);
            float corr = __expf(m_i[i] - mnew);   // 0 on first tile
            float rs = 0.f;
            #pragma unroll
            for (int j = 0; j < 4; j++) {
                float p = __expf(s[i][j] - mnew);
                s[i][j] = p;
                rs += p;
            }
            rs += __shfl_xor_sync(0xffffffffu, rs, 8);
            rs += __shfl_xor_sync(0xffffffffu, rs, 4);
            rs += __shfl_xor_sync(0xffffffffu, rs, 2);
            rs += __shfl_xor_sync(0xffffffffu, rs, 1);
            l_i[i] = l_i[i] * corr + rs;
            m_i[i] = mnew;
            if (tx == 0) corr_s[ty * 8 + i] = corr;
            *(float4*)&Ps[ty * 8 + i][tx * 4] =
                make_float4(s[i][0], s[i][1], s[i][2], s[i][3]);
        }
        __syncthreads();

        // ---- Z += P * x_k : 4q x 4c per thread, c-paired FFMA2 ----
        #pragma unroll
        for (int i = 0; i < 4; i++) {
            float cr = corr_s[zr + i];
            ull cp = pack2(cr, cr);
            mul2(z2[i][0], cp);
            mul2(z2[i][1], cp);
        }

        #pragma unroll 4
        for (int k4 = 0; k4 < 16; k4++) {
            float4 xv[4], pr[4];
            #pragma unroll
            for (int kk = 0; kk < 4; kk++)
                xv[kk] = *(const float4*)&xN[k4 * 4 + kk][zc];
            #pragma unroll
            for (int i = 0; i < 4; i++)
                pr[i] = *(const float4*)&Ps[zr + i][k4 * 4];

            ull xlo[4], xhi[4];
            #pragma unroll
            for (int kk = 0; kk < 4; kk++) {
                xlo[kk] = pack2(xv[kk].x, xv[kk].y);
                xhi[kk] = pack2(xv[kk].z, xv[kk].w);
            }
            #pragma unroll
            for (int i = 0; i < 4; i++) {
                const float* pv = (const float*)&pr[i];
                #pragma unroll
                for (int kk = 0; kk < 4; kk++) {
                    ull pd = pack2(pv[kk], pv[kk]);
                    fma2(z2[i][0], pd, xlo[kk]);
                    fma2(z2[i][1], pd, xhi[kk]);
                }
            }
        }
    }

    // ---- epilogue: out = (Z / l) * Wv ----
    if (tx == 0) {
        #pragma unroll
        for (int i = 0; i < 8; i++) linv_s[ty * 8 + i] = 1.f / l_i[i];
    }
    __syncthreads();   // Z-pass reads of Ps done; linv visible

    #pragma unroll
    for (int i = 0; i < 4; i++) {
        float li = linv_s[zr + i];
        float2 a = unpack2(z2[i][0]);
        float2 c = unpack2(z2[i][1]);
        *(float4*)&Ps[zr + i][zc] =
            make_float4(a.x * li, a.y * li, c.x * li, c.y * li);
    }
    {   // load Wv [32][64] into xT
        const float4* wg = (const float4*)Wv;
        #pragma unroll
        for (int it = 0; it < 4; it++) {
            int lin = tid + it * 128;           // 0..511
            int r = lin >> 4, c4 = lin & 15;
            *(float4*)&xT[r][c4 * 4] = wg[lin];
        }
    }
    __syncthreads();

    float o[8][4];
    #pragma unroll
    for (int i = 0; i < 8; i++)
        #pragma unroll
        for (int j = 0; j < 4; j++) o[i][j] = 0.f;

    #pragma unroll 4
    for (int c = 0; c < C_; c++) {
        float4 w4 = *(const float4*)&xT[c][tx * 4];
        #pragma unroll
        for (int i = 0; i < 8; i++) {
            float zv = Ps[ty * 8 + i][c];
            o[i][0] += zv * w4.x; o[i][1] += zv * w4.y;
            o[i][2] += zv * w4.z; o[i][3] += zv * w4.w;
        }
    }

    float* Og = out + (b * T_ + qt * 64) * D_;
    #pragma unroll
    for (int i = 0; i < 8; i++)
        *(float4*)&Og[(ty * 8 + i) * D_ + tx * 4] =
            make_float4(o[i][0], o[i][1], o[i][2], o[i][3]);
}

// ---------------------------------------------------------------------------
extern "C" void kernel_launch(void* const* d_in, const int* in_sizes, int n_in,
                              void* d_out, int out_size)
{
    const float* x  = (const float*)d_in[0];
    const float* Wk = (const float*)d_in[1];
    const float* Wq = (const float*)d_in[2];
    const float* Wv = (const float*)d_in[3];
    float* out = (float*)d_out;

    m_kernel<<<1, 1024>>>(Wk, Wq);
    attn_kernel<<<dim3(NQT, B_), 128>>>(x, Wv, out);
}